// round 14
// baseline (speedup 1.0000x reference)
#include <cuda_runtime.h>
#include <math.h>
#include <stdint.h>

#define BB 32
#define LL 196
#define DD 512
#define HH 512
#define EE 256
#define TT 128
#define VV 512
#define A1 256
#define A2 128
#define GG 2048            // 4*H
#define NH 358
#define HZE (HH + DD + EE) // 1280
#define NPG (A1 + GG)      // 2304
#define PADTOK 0
#define NBLK 296
#define NTHR 256
#define NGRP 37            // 296 / 8
#define XPA 260            // x1t (tf32) row stride: conflict-free a-frag LDS

// ---------------- scratch (no allocation allowed) ----------------
__device__ float g_eseq[BB * TT * EE];
__device__ float g_prea[BB * LL * A1];
__device__ float g_egate[BB * TT * GG];
__device__ float g_h[BB * HH];
__device__ float g_c[BB * HH];
__device__ float g_hpg[BB * NPG];
__device__ float g_scores[BB * LL];
__device__ float g_z[BB * DD];
__device__ float g_hze[BB * TT * HZE];
__device__ float g_x1[BB * TT * NH];
__device__ float g_x2[BB * TT * NH];
__device__ uint32_t g_w2t[A1 * A2];      // att_w2 tf32  [k*128+n]
__device__ uint32_t g_w1ht[HH * A1];     // att_w1[D:] tf32 [k*256+n]
__device__ uint32_t g_whht[HH * GG];     // w_hh tf32 [k*2048+n]
__device__ uint32_t g_wiht[DD * GG];     // w_ih[:D] tf32 [k*2048+n]
__device__ uint32_t g_htf[BB * HH];      // h as tf32
__device__ uint32_t g_ztf[BB * DD];      // z as tf32

// ---------------- hierarchical grid barrier (generation-tagged) ----------------
__device__ unsigned g_cnt0[NGRP];
__device__ unsigned g_cnt1;
__device__ volatile unsigned g_bar_gen;

__device__ __forceinline__ void grid_sync() {
    __syncthreads();
    if (threadIdx.x == 0) {
        unsigned gen = g_bar_gen;
        __threadfence();
        unsigned grp = (unsigned)blockIdx.x >> 3;
        unsigned old = atomicAdd(&g_cnt0[grp], 1u);
        bool done = false;
        if (old == 8u * gen + 7u) {
            unsigned o1 = atomicAdd(&g_cnt1, 1u);
            if (o1 == (unsigned)NGRP * gen + (NGRP - 1u)) {
                __threadfence();
                g_bar_gen = gen + 1u;
                done = true;
            }
        }
        if (!done) while (g_bar_gen == gen) {}
        __threadfence();
    }
    __syncthreads();
}

__device__ __forceinline__ float tanh_fast(float x) {
    float y;
    asm("tanh.approx.f32 %0, %1;" : "=f"(y) : "f"(x));
    return y;
}

__device__ __forceinline__ uint32_t f2tf32(float x) {
    uint32_t r;
    asm("cvt.rna.tf32.f32 %0, %1;" : "=r"(r) : "f"(x));
    return r;
}

__device__ __forceinline__ void mma_tf32(float c[4], uint32_t a0, uint32_t a1,
                                         uint32_t a2, uint32_t a3,
                                         uint32_t b0, uint32_t b1) {
    asm volatile(
        "mma.sync.aligned.m16n8k8.row.col.f32.tf32.tf32.f32 "
        "{%0,%1,%2,%3}, {%4,%5,%6,%7}, {%8,%9}, {%0,%1,%2,%3};"
        : "+f"(c[0]), "+f"(c[1]), "+f"(c[2]), "+f"(c[3])
        : "r"(a0), "r"(a1), "r"(a2), "r"(a3), "r"(b0), "r"(b1));
}

// ---------------- weight -> tf32 conversion (once per launch) ----------------
__global__ void k_cvt(uint32_t* __restrict__ dst, const float* __restrict__ src) {
    int i = blockIdx.x * 256 + threadIdx.x;
    dst[i] = f2tf32(src[i]);
}

// ---------------- embedding gather (shift-right w/ pad) ----------------
__global__ void k_embed(const int* __restrict__ y, const float* __restrict__ embed) {
    int bt = blockIdx.x;
    int b = bt / TT, t = bt % TT;
    int tok = (t == 0) ? PADTOK : y[b * TT + (t - 1)];
    float v = embed[tok * EE + threadIdx.x];
    g_eseq[bt * EE + threadIdx.x] = v;
    g_hze[bt * HZE + HH + DD + threadIdx.x] = v;
}

// ---------------- generic tiled SGEMM: C = act(A*W + bias) ----------------
template <int ACT>
__global__ void k_sgemm(const float* __restrict__ A, int lda,
                        const float* __restrict__ W, int ldw,
                        const float* __restrict__ bias,
                        float* __restrict__ C, int ldc,
                        int M, int N, int K) {
    __shared__ float As[16][65];
    __shared__ float Ws[16][65];
    int tx = threadIdx.x % 16, ty = threadIdx.x / 16;
    int row0 = blockIdx.y * 64;
    int col0 = blockIdx.x * 64;
    float acc[4][4] = {};
    for (int k0 = 0; k0 < K; k0 += 16) {
        for (int i = threadIdx.x; i < 64 * 16; i += 256) {
            int r = i >> 4, kk = i & 15;
            int gr = row0 + r, gk = k0 + kk;
            As[kk][r] = (gr < M && gk < K) ? A[gr * lda + gk] : 0.f;
        }
        for (int i = threadIdx.x; i < 16 * 64; i += 256) {
            int kk = i >> 6, c = i & 63;
            int gk = k0 + kk, gc = col0 + c;
            Ws[kk][c] = (gk < K && gc < N) ? W[gk * ldw + gc] : 0.f;
        }
        __syncthreads();
#pragma unroll
        for (int kk = 0; kk < 16; kk++) {
            float a_[4], w_[4];
#pragma unroll
            for (int i = 0; i < 4; i++) a_[i] = As[kk][ty * 4 + i];
#pragma unroll
            for (int j = 0; j < 4; j++) w_[j] = Ws[kk][tx * 4 + j];
#pragma unroll
            for (int i = 0; i < 4; i++)
#pragma unroll
                for (int j = 0; j < 4; j++) acc[i][j] += a_[i] * w_[j];
        }
        __syncthreads();
    }
#pragma unroll
    for (int i = 0; i < 4; i++) {
        int r = row0 + ty * 4 + i;
        if (r >= M) continue;
#pragma unroll
        for (int j = 0; j < 4; j++) {
            int c = col0 + tx * 4 + j;
            if (c >= N) continue;
            float v = acc[i][j] + (bias ? bias[c] : 0.f);
            if (ACT == 1) v = tanhf(v);
            C[r * ldc + c] = v;
        }
    }
}

// ---------------- persistent step-loop kernel ----------------
struct SmemBm { uint32_t x1t[32][XPA]; float red[32][4]; };         // ~34 KB
struct SmemC  { float al[LL]; float red[8]; float cpart[2][128]; };
union StepSmem { SmemBm bm; SmemC c; };

__global__ __launch_bounds__(NTHR, 2)
void k_steps(const float* __restrict__ a_feat,
             const float* __restrict__ h0, const float* __restrict__ c0,
             const float* __restrict__ bhh,
             const float* __restrict__ b2,
             const float* __restrict__ w3, const float* __restrict__ b3) {
    __shared__ StepSmem sm;
    int bid = blockIdx.x;
    int tid = threadIdx.x;
    int lane = tid & 31, w = tid >> 5;
    int gid = lane >> 2, tig = lane & 3;

    for (int i = bid * NTHR + tid; i < BB * HH; i += NBLK * NTHR) {
        float hv = h0[i];
        g_h[i] = hv;
        g_htf[i] = f2tf32(hv);
        g_c[i] = c0[i];
    }
    grid_sync();

    for (int t = 0; t < TT; t++) {
        // ======== P1: mma projections.
        //   blocks 0..7   : A1  hpg[:, 0:256]   = h @ w1h        (8 units m32 x n32)
        //   blocks 8..71  : A2  hpg[:, 256:2304]= h @ whh + bhh  (64 units m32 x n32)
        if (bid < 72) {
            bool isA1 = (bid < 8);
            int n0u = isA1 ? bid * 32 : (bid - 8) * 32;
            int wm = w & 1, wn = w >> 1;
            int nw = n0u + wn * 8;          // warp's n8 base
            int rlo = wm * 16 + gid;        // batch rows
            const uint32_t* Wt = isA1 ? g_w1ht : g_whht;
            int ldb = isA1 ? A1 : GG;
            float cfr[4] = {};
#pragma unroll 8
            for (int ks = 0; ks < 64; ks++) {
                int k0 = ks * 8;
                uint32_t a0 = g_htf[rlo * HH + k0 + tig];
                uint32_t a1 = g_htf[(rlo + 8) * HH + k0 + tig];
                uint32_t a2r = g_htf[rlo * HH + k0 + tig + 4];
                uint32_t a3 = g_htf[(rlo + 8) * HH + k0 + tig + 4];
                uint32_t b0 = Wt[(k0 + tig) * ldb + nw + gid];
                uint32_t b1 = Wt[(k0 + tig + 4) * ldb + nw + gid];
                mma_tf32(cfr, a0, a1, a2r, a3, b0, b1);
            }
            int cA = nw + tig * 2;
            if (isA1) {
                g_hpg[rlo * NPG + cA] = cfr[0];
                g_hpg[rlo * NPG + cA + 1] = cfr[1];
                g_hpg[(rlo + 8) * NPG + cA] = cfr[2];
                g_hpg[(rlo + 8) * NPG + cA + 1] = cfr[3];
            } else {
                float bA = bhh[cA], bB = bhh[cA + 1];
                g_hpg[rlo * NPG + A1 + cA] = cfr[0] + bA;
                g_hpg[rlo * NPG + A1 + cA + 1] = cfr[1] + bB;
                g_hpg[(rlo + 8) * NPG + A1 + cA] = cfr[2] + bA;
                g_hpg[(rlo + 8) * NPG + A1 + cA + 1] = cfr[3] + bB;
            }
        }
        grid_sync();

        // ======== P2: attention via tf32 mma (224 units = 32 b x 7 l-tiles(32))
        if (bid < 224) {
            int b = bid / 7;
            int l0 = (bid % 7) * 32;
            {
                float hpk = g_hpg[b * NPG + tid];     // k = tid (A1 == NTHR)
                const float* pr = g_prea + (size_t)(b * LL + l0) * A1 + tid;
#pragma unroll 8
                for (int r = 0; r < 32; r++) {
                    int l = l0 + r;
                    float v = 0.f;
                    if (l < LL) v = tanh_fast(__ldcg(&pr[(size_t)r * A1]) + hpk);
                    sm.bm.x1t[r][tid] = f2tf32(v);
                }
            }
            __syncthreads();
            int wm = w & 1;                 // m16 tile (0/1)
            int wn = w >> 1;                // n32 block (0..3)
            int ra = wm * 16;
            float cfr[4][4] = {};           // [nt][reg]
#pragma unroll 4
            for (int ks = 0; ks < 32; ks++) {
                int k0 = ks * 8;
                uint32_t a0 = sm.bm.x1t[ra + gid][k0 + tig];
                uint32_t a1 = sm.bm.x1t[ra + gid + 8][k0 + tig];
                uint32_t a2r = sm.bm.x1t[ra + gid][k0 + tig + 4];
                uint32_t a3 = sm.bm.x1t[ra + gid + 8][k0 + tig + 4];
                const uint32_t* wb0 = &g_w2t[(k0 + tig) * A2 + wn * 32 + gid];
                const uint32_t* wb1 = &g_w2t[(k0 + tig + 4) * A2 + wn * 32 + gid];
#pragma unroll
                for (int nt = 0; nt < 4; nt++) {
                    uint32_t b0 = wb0[nt * 8];
                    uint32_t b1 = wb1[nt * 8];
                    mma_tf32(cfr[nt], a0, a1, a2r, a3, b0, b1);
                }
            }
            float p_lo = 0.f, p_hi = 0.f;
#pragma unroll
            for (int nt = 0; nt < 4; nt++) {
                int cA = wn * 32 + nt * 8 + tig * 2;
                float b2a = b2[cA], b2b = b2[cA + 1];
                float w3a = w3[cA], w3b = w3[cA + 1];
                p_lo += tanh_fast(cfr[nt][0] + b2a) * w3a + tanh_fast(cfr[nt][1] + b2b) * w3b;
                p_hi += tanh_fast(cfr[nt][2] + b2a) * w3a + tanh_fast(cfr[nt][3] + b2b) * w3b;
            }
            p_lo += __shfl_down_sync(0xffffffffu, p_lo, 2, 4);
            p_lo += __shfl_down_sync(0xffffffffu, p_lo, 1, 4);
            p_hi += __shfl_down_sync(0xffffffffu, p_hi, 2, 4);
            p_hi += __shfl_down_sync(0xffffffffu, p_hi, 1, 4);
            if (tig == 0) {
                sm.bm.red[ra + gid][wn] = p_lo;
                sm.bm.red[ra + gid + 8][wn] = p_hi;
            }
            __syncthreads();
            if (tid < 32) {
                int l = l0 + tid;
                if (l < LL) {
                    float s = sm.bm.red[tid][0] + sm.bm.red[tid][1]
                            + sm.bm.red[tid][2] + sm.bm.red[tid][3] + b3[0];
                    g_scores[b * LL + l] = s;
                }
            }
        }
        grid_sync();

        // ======== P3: softmax + z (128 units = 32 b x 4 d-chunks(128)) ========
        if (bid < 128) {
            int b = bid >> 2;
            int dch = bid & 3;
            int warp = w;
            float v = (tid < LL) ? g_scores[b * LL + tid] : -1e30f;
            float m = v;
#pragma unroll
            for (int off = 16; off; off >>= 1) m = fmaxf(m, __shfl_xor_sync(0xffffffffu, m, off));
            if (lane == 0) sm.c.red[warp] = m;
            __syncthreads();
            m = sm.c.red[0];
#pragma unroll
            for (int i = 1; i < 8; i++) m = fmaxf(m, sm.c.red[i]);
            float e = (tid < LL) ? expf(v - m) : 0.f;
            __syncthreads();
            float sum = e;
#pragma unroll
            for (int off = 16; off; off >>= 1) sum += __shfl_xor_sync(0xffffffffu, sum, off);
            if (lane == 0) sm.c.red[warp] = sum;
            __syncthreads();
            sum = sm.c.red[0] + sm.c.red[1] + sm.c.red[2] + sm.c.red[3]
                + sm.c.red[4] + sm.c.red[5] + sm.c.red[6] + sm.c.red[7];
            float inv = 1.f / sum;
            if (tid < LL) sm.c.al[tid] = e * inv;
            __syncthreads();
            int dl = tid & 127;
            int lh = tid >> 7;
            int d = dch * 128 + dl;
            const float* ab = a_feat + (size_t)(b * LL + lh * 98) * DD + d;
            const float* alv = &sm.c.al[lh * 98];
            float acc = 0.f;
#pragma unroll 14
            for (int l = 0; l < 98; l++) acc += alv[l] * __ldcg(&ab[(size_t)l * DD]);
            sm.c.cpart[lh][dl] = acc;
            __syncthreads();
            if (tid < 128) {
                float zv = sm.c.cpart[0][tid] + sm.c.cpart[1][tid];
                int dg = dch * 128 + tid;
                g_z[b * DD + dg] = zv;
                g_ztf[b * DD + dg] = f2tf32(zv);
                g_hze[(size_t)(b * TT + t) * HZE + HH + dg] = zv;
            }
        }
        grid_sync();

        // ======== P4: LSTM via mma (16 units = 32-jp chunks) ==================
        // warp = m16 x 4 gate-tiles at n = gate*512 + jp-slice. Each lane ends
        // with i,f,g,o for its (batch, jp) cells in-register -> pointwise inline.
        if (bid < 16) {
            int wm = w & 1, grp = w >> 1;           // 2 m-tiles x 4 jp-groups(8)
            int jpb = bid * 32 + grp * 8;           // warp's jp8 base
            int rlo = wm * 16 + gid;                // batch rows rlo, rlo+8
            float cfr[4][4] = {};                   // [gate][reg]
#pragma unroll 4
            for (int ks = 0; ks < 64; ks++) {
                int k0 = ks * 8;
                uint32_t a0 = g_ztf[rlo * DD + k0 + tig];
                uint32_t a1 = g_ztf[(rlo + 8) * DD + k0 + tig];
                uint32_t a2r = g_ztf[rlo * DD + k0 + tig + 4];
                uint32_t a3 = g_ztf[(rlo + 8) * DD + k0 + tig + 4];
                const uint32_t* wb0 = &g_wiht[(k0 + tig) * GG + jpb + gid];
                const uint32_t* wb1 = &g_wiht[(k0 + tig + 4) * GG + jpb + gid];
#pragma unroll
                for (int gate = 0; gate < 4; gate++) {
                    uint32_t b0 = wb0[gate * 512];
                    uint32_t b1 = wb1[gate * 512];
                    mma_tf32(cfr[gate], a0, a1, a2r, a3, b0, b1);
                }
            }
            // pointwise: lane covers rows {rlo, rlo+8} x cols {jpb+tig*2, +1}
#pragma unroll
            for (int half = 0; half < 2; half++) {
                int b = rlo + half * 8;
                int creg = half * 2;                 // c[creg], c[creg+1]
                const float* eg = g_egate + (size_t)(b * TT + t) * GG;
                const float* hg = g_hpg + b * NPG + A1;
#pragma unroll
                for (int jj = 0; jj < 2; jj++) {
                    int jp = jpb + tig * 2 + jj;
                    float ai = cfr[0][creg + jj] + eg[jp]        + hg[jp];
                    float af = cfr[1][creg + jj] + eg[jp + 512]  + hg[jp + 512];
                    float ag = cfr[2][creg + jj] + eg[jp + 1024] + hg[jp + 1024];
                    float ao = cfr[3][creg + jj] + eg[jp + 1536] + hg[jp + 1536];
                    float i_ = 1.f / (1.f + expf(-ai));
                    float f_ = 1.f / (1.f + expf(-af));
                    float o_ = 1.f / (1.f + expf(-ao));
                    float gv = tanhf(ag);
                    float c = f_ * g_c[b * HH + jp] + i_ * gv;
                    float h = o_ * tanhf(c);
                    g_c[b * HH + jp] = c;
                    g_h[b * HH + jp] = h;
                    g_htf[b * HH + jp] = f2tf32(h);
                    g_hze[(size_t)(b * TT + t) * HZE + jp] = h;
                }
            }
        }
        grid_sync();
    }
}

// ---------------- launch ----------------
extern "C" void kernel_launch(void* const* d_in, const int* in_sizes, int n_in,
                              void* d_out, int out_size) {
    const float* a      = (const float*)d_in[0];
    const float* h0     = (const float*)d_in[1];
    const float* c0     = (const float*)d_in[2];
    const int*   y      = (const int*)d_in[3];
    const float* att_w1 = (const float*)d_in[4];
    const float* att_b1 = (const float*)d_in[5];
    const float* att_w2 = (const float*)d_in[6];
    const float* att_b2 = (const float*)d_in[7];
    const float* att_w3 = (const float*)d_in[8];
    const float* att_b3 = (const float*)d_in[9];
    const float* w_ih   = (const float*)d_in[10];
    const float* w_hh   = (const float*)d_in[11];
    const float* b_ih   = (const float*)d_in[12];
    const float* b_hh   = (const float*)d_in[13];
    const float* embed  = (const float*)d_in[14];
    const float* out_w1 = (const float*)d_in[15];
    const float* out_b1 = (const float*)d_in[16];
    const float* out_w2 = (const float*)d_in[17];
    const float* out_b2 = (const float*)d_in[18];
    const float* out_w3 = (const float*)d_in[19];
    const float* out_b3 = (const float*)d_in[20];
    float* out = (float*)d_out;

    float *prea, *eseq, *egate, *hze, *x1, *x2;
    uint32_t *w2t, *w1ht, *whht, *wiht;
    cudaGetSymbolAddress((void**)&prea,  g_prea);
    cudaGetSymbolAddress((void**)&eseq,  g_eseq);
    cudaGetSymbolAddress((void**)&egate, g_egate);
    cudaGetSymbolAddress((void**)&hze,   g_hze);
    cudaGetSymbolAddress((void**)&x1,    g_x1);
    cudaGetSymbolAddress((void**)&x2,    g_x2);
    cudaGetSymbolAddress((void**)&w2t,   g_w2t);
    cudaGetSymbolAddress((void**)&w1ht,  g_w1ht);
    cudaGetSymbolAddress((void**)&whht,  g_whht);
    cudaGetSymbolAddress((void**)&wiht,  g_wiht);

    k_embed<<<BB * TT, EE>>>(y, embed);
    k_cvt<<<(A1 * A2) / 256, 256>>>(w2t, att_w2);
    k_cvt<<<(HH * A1) / 256, 256>>>(w1ht, att_w1 + (size_t)DD * A1);
    k_cvt<<<(HH * GG) / 256, 256>>>(whht, w_hh);
    k_cvt<<<(DD * GG) / 256, 256>>>(wiht, w_ih);

    k_sgemm<0><<<dim3((A1 + 63) / 64, (BB * LL + 63) / 64), 256>>>(
        a, DD, att_w1, A1, att_b1, prea, A1, BB * LL, A1, DD);
    k_sgemm<0><<<dim3((GG + 63) / 64, (BB * TT + 63) / 64), 256>>>(
        eseq, EE, w_ih + (size_t)DD * GG, GG, b_ih, egate, GG, BB * TT, GG, EE);

    k_steps<<<NBLK, NTHR>>>(a, h0, c0, b_hh, att_b2, att_w3, att_b3);

    k_sgemm<1><<<dim3((NH + 63) / 64, (BB * TT + 63) / 64), 256>>>(
        hze, HZE, out_w1, NH, out_b1, x1, NH, BB * TT, NH, HZE);
    k_sgemm<1><<<dim3((NH + 63) / 64, (BB * TT + 63) / 64), 256>>>(
        x1, NH, out_w2, NH, out_b2, x2, NH, BB * TT, NH, NH);
    k_sgemm<0><<<dim3((VV + 63) / 64, (BB * TT + 63) / 64), 256>>>(
        x2, NH, out_w3, VV, out_b3, out, VV, BB * TT, VV, NH);
}

// round 15
// speedup vs baseline: 1.6825x; 1.6825x over previous
#include <cuda_runtime.h>
#include <math.h>
#include <stdint.h>

#define BB 32
#define LL 196
#define DD 512
#define HH 512
#define EE 256
#define TT 128
#define VV 512
#define A1 256
#define A2 128
#define GG 2048            // 4*H
#define NH 358
#define HZE (HH + DD + EE) // 1280
#define NPG (A1 + GG)      // 2304
#define PADTOK 0
#define NBLK 296
#define NTHR 256
#define NGRP 37            // 296 / 8
#define XPA 260            // x1t row stride (tf32), conflict-free a-frag LDS
#define HP 516             // h/z 16-row tile stride: 516 mod 32 = 4 -> conflict-free

// ---------------- scratch (no allocation allowed) ----------------
__device__ float g_eseq[BB * TT * EE];
__device__ float g_prea[BB * LL * A1];
__device__ float g_egate[BB * TT * GG];
__device__ float g_h[BB * HH];
__device__ float g_c[BB * HH];
__device__ float g_hpg[BB * NPG];
__device__ float g_scores[BB * LL];
__device__ float g_z[BB * DD];
__device__ float g_hze[BB * TT * HZE];
__device__ float g_x1[BB * TT * NH];
__device__ float g_x2[BB * TT * NH];
__device__ uint32_t g_w2t[A1 * A2];      // att_w2 tf32  [k*128+n]
__device__ uint32_t g_w1ht[HH * A1];     // att_w1[D:] tf32 [k*256+n]
__device__ uint32_t g_whht[HH * GG];     // w_hh tf32 [k*2048+n]
__device__ uint32_t g_wiht[DD * GG];     // w_ih[:D] tf32 [k*2048+n]

// ---------------- hierarchical grid barrier (generation-tagged) ----------------
__device__ unsigned g_cnt0[NGRP];
__device__ unsigned g_cnt1;
__device__ volatile unsigned g_bar_gen;

__device__ __forceinline__ void grid_sync() {
    __syncthreads();
    if (threadIdx.x == 0) {
        unsigned gen = g_bar_gen;
        __threadfence();
        unsigned grp = (unsigned)blockIdx.x >> 3;
        unsigned old = atomicAdd(&g_cnt0[grp], 1u);
        bool done = false;
        if (old == 8u * gen + 7u) {
            unsigned o1 = atomicAdd(&g_cnt1, 1u);
            if (o1 == (unsigned)NGRP * gen + (NGRP - 1u)) {
                __threadfence();
                g_bar_gen = gen + 1u;
                done = true;
            }
        }
        if (!done) while (g_bar_gen == gen) {}
        __threadfence();
    }
    __syncthreads();
}

__device__ __forceinline__ float tanh_fast(float x) {
    float y;
    asm("tanh.approx.f32 %0, %1;" : "=f"(y) : "f"(x));
    return y;
}

__device__ __forceinline__ uint32_t f2tf32(float x) {
    uint32_t r;
    asm("cvt.rna.tf32.f32 %0, %1;" : "=r"(r) : "f"(x));
    return r;
}

__device__ __forceinline__ void mma_tf32(float c[4], uint32_t a0, uint32_t a1,
                                         uint32_t a2, uint32_t a3,
                                         uint32_t b0, uint32_t b1) {
    asm volatile(
        "mma.sync.aligned.m16n8k8.row.col.f32.tf32.tf32.f32 "
        "{%0,%1,%2,%3}, {%4,%5,%6,%7}, {%8,%9}, {%0,%1,%2,%3};"
        : "+f"(c[0]), "+f"(c[1]), "+f"(c[2]), "+f"(c[3])
        : "r"(a0), "r"(a1), "r"(a2), "r"(a3), "r"(b0), "r"(b1));
}

// ---------------- weight -> tf32 conversion (once per launch) ----------------
__global__ void k_cvt(uint32_t* __restrict__ dst, const float* __restrict__ src) {
    int i = blockIdx.x * 256 + threadIdx.x;
    dst[i] = f2tf32(src[i]);
}

// ---------------- embedding gather (shift-right w/ pad) ----------------
__global__ void k_embed(const int* __restrict__ y, const float* __restrict__ embed) {
    int bt = blockIdx.x;
    int b = bt / TT, t = bt % TT;
    int tok = (t == 0) ? PADTOK : y[b * TT + (t - 1)];
    float v = embed[tok * EE + threadIdx.x];
    g_eseq[bt * EE + threadIdx.x] = v;
    g_hze[bt * HZE + HH + DD + threadIdx.x] = v;
}

// ---------------- generic tiled SGEMM: C = act(A*W + bias) ----------------
template <int ACT>
__global__ void k_sgemm(const float* __restrict__ A, int lda,
                        const float* __restrict__ W, int ldw,
                        const float* __restrict__ bias,
                        float* __restrict__ C, int ldc,
                        int M, int N, int K) {
    __shared__ float As[16][65];
    __shared__ float Ws[16][65];
    int tx = threadIdx.x % 16, ty = threadIdx.x / 16;
    int row0 = blockIdx.y * 64;
    int col0 = blockIdx.x * 64;
    float acc[4][4] = {};
    for (int k0 = 0; k0 < K; k0 += 16) {
        for (int i = threadIdx.x; i < 64 * 16; i += 256) {
            int r = i >> 4, kk = i & 15;
            int gr = row0 + r, gk = k0 + kk;
            As[kk][r] = (gr < M && gk < K) ? A[gr * lda + gk] : 0.f;
        }
        for (int i = threadIdx.x; i < 16 * 64; i += 256) {
            int kk = i >> 6, c = i & 63;
            int gk = k0 + kk, gc = col0 + c;
            Ws[kk][c] = (gk < K && gc < N) ? W[gk * ldw + gc] : 0.f;
        }
        __syncthreads();
#pragma unroll
        for (int kk = 0; kk < 16; kk++) {
            float a_[4], w_[4];
#pragma unroll
            for (int i = 0; i < 4; i++) a_[i] = As[kk][ty * 4 + i];
#pragma unroll
            for (int j = 0; j < 4; j++) w_[j] = Ws[kk][tx * 4 + j];
#pragma unroll
            for (int i = 0; i < 4; i++)
#pragma unroll
                for (int j = 0; j < 4; j++) acc[i][j] += a_[i] * w_[j];
        }
        __syncthreads();
    }
#pragma unroll
    for (int i = 0; i < 4; i++) {
        int r = row0 + ty * 4 + i;
        if (r >= M) continue;
#pragma unroll
        for (int j = 0; j < 4; j++) {
            int c = col0 + tx * 4 + j;
            if (c >= N) continue;
            float v = acc[i][j] + (bias ? bias[c] : 0.f);
            if (ACT == 1) v = tanhf(v);
            C[r * ldc + c] = v;
        }
    }
}

// ---------------- persistent step-loop kernel ----------------
struct SmemBm { uint32_t x1t[32][XPA]; float red[32][4]; };         // ~34 KB
struct SmemC  { float al[LL]; float red[8]; float cpart[2][128]; };
struct SmemT  { uint32_t a16[16][HP]; };                            // 33 KB (h or z tile)
union StepSmem { SmemBm bm; SmemC c; SmemT tt; };

__global__ __launch_bounds__(NTHR, 2)
void k_steps(const float* __restrict__ a_feat,
             const float* __restrict__ h0, const float* __restrict__ c0,
             const float* __restrict__ bhh,
             const float* __restrict__ b2,
             const float* __restrict__ w3, const float* __restrict__ b3) {
    __shared__ StepSmem sm;
    int bid = blockIdx.x;
    int tid = threadIdx.x;
    int lane = tid & 31, w = tid >> 5;
    int gid = lane >> 2, tig = lane & 3;

    for (int i = bid * NTHR + tid; i < BB * HH; i += NBLK * NTHR) {
        g_h[i] = h0[i];
        g_c[i] = c0[i];
    }
    grid_sync();

    for (int t = 0; t < TT; t++) {
        // ======== P1: h projections via mma (72 blocks = 2 m-halves x 36 n-blocks)
        // hpg[:, 0:256] = h @ w1h ; hpg[:, 256:2304] = h @ whh + bhh
        if (bid < 72) {
            int mh = (bid < 36) ? 0 : 1;
            int nblk = (bid < 36) ? bid : bid - 36;
            // stage h[mh*16 .. +15][0:512] as tf32, stride HP (conflict-free)
            for (int i = tid; i < 16 * HH; i += NTHR) {
                int r = i >> 9, k = i & 511;
                sm.tt.a16[r][k] = f2tf32(g_h[(mh * 16 + r) * HH + k]);
            }
            __syncthreads();
            int nb = nblk * 8 + w;            // n8-tile index 0..287
            int n0 = nb * 8;                  // col base in 0..2303
            bool isA1 = (n0 < A1);
            const uint32_t* Wt = isA1 ? g_w1ht : g_whht;
            int ldb = isA1 ? A1 : GG;
            int cb = isA1 ? n0 : (n0 - A1);   // col base within weight
            float cfr[4] = {};
#pragma unroll 8
            for (int ks = 0; ks < 64; ks++) {
                int k0 = ks * 8;
                uint32_t a0 = sm.tt.a16[gid][k0 + tig];
                uint32_t a1 = sm.tt.a16[gid + 8][k0 + tig];
                uint32_t a2r = sm.tt.a16[gid][k0 + tig + 4];
                uint32_t a3 = sm.tt.a16[gid + 8][k0 + tig + 4];
                uint32_t b0 = Wt[(k0 + tig) * ldb + cb + gid];
                uint32_t b1 = Wt[(k0 + tig + 4) * ldb + cb + gid];
                mma_tf32(cfr, a0, a1, a2r, a3, b0, b1);
            }
            int n = n0 + tig * 2;             // output col (n-space 0..2303)
            int blo = mh * 16 + gid;
            float bA = isA1 ? 0.f : bhh[n - A1];
            float bB = isA1 ? 0.f : bhh[n + 1 - A1];
            g_hpg[blo * NPG + n] = cfr[0] + bA;
            g_hpg[blo * NPG + n + 1] = cfr[1] + bB;
            g_hpg[(blo + 8) * NPG + n] = cfr[2] + bA;
            g_hpg[(blo + 8) * NPG + n + 1] = cfr[3] + bB;
            __syncthreads();
        }
        grid_sync();

        // ======== P2: attention via tf32 mma (224 units = 32 b x 7 l-tiles(32))
        if (bid < 224) {
            int b = bid / 7;
            int l0 = (bid % 7) * 32;
            {
                float hpk = g_hpg[b * NPG + tid];     // k = tid (A1 == NTHR)
                const float* pr = g_prea + (size_t)(b * LL + l0) * A1 + tid;
#pragma unroll 8
                for (int r = 0; r < 32; r++) {
                    int l = l0 + r;
                    float v = 0.f;
                    if (l < LL) v = tanh_fast(__ldcg(&pr[(size_t)r * A1]) + hpk);
                    sm.bm.x1t[r][tid] = f2tf32(v);
                }
            }
            __syncthreads();
            int wm = w & 1;                 // m16 tile (0/1)
            int wn = w >> 1;                // n32 block (0..3)
            int ra = wm * 16;
            float cfr[4][4] = {};           // [nt][reg]
#pragma unroll 4
            for (int ks = 0; ks < 32; ks++) {
                int k0 = ks * 8;
                uint32_t a0 = sm.bm.x1t[ra + gid][k0 + tig];
                uint32_t a1 = sm.bm.x1t[ra + gid + 8][k0 + tig];
                uint32_t a2r = sm.bm.x1t[ra + gid][k0 + tig + 4];
                uint32_t a3 = sm.bm.x1t[ra + gid + 8][k0 + tig + 4];
                const uint32_t* wb0 = &g_w2t[(k0 + tig) * A2 + wn * 32 + gid];
                const uint32_t* wb1 = &g_w2t[(k0 + tig + 4) * A2 + wn * 32 + gid];
#pragma unroll
                for (int nt = 0; nt < 4; nt++) {
                    uint32_t b0 = wb0[nt * 8];
                    uint32_t b1 = wb1[nt * 8];
                    mma_tf32(cfr[nt], a0, a1, a2r, a3, b0, b1);
                }
            }
            float p_lo = 0.f, p_hi = 0.f;
#pragma unroll
            for (int nt = 0; nt < 4; nt++) {
                int cA = wn * 32 + nt * 8 + tig * 2;
                float b2a = b2[cA], b2b = b2[cA + 1];
                float w3a = w3[cA], w3b = w3[cA + 1];
                p_lo += tanh_fast(cfr[nt][0] + b2a) * w3a + tanh_fast(cfr[nt][1] + b2b) * w3b;
                p_hi += tanh_fast(cfr[nt][2] + b2a) * w3a + tanh_fast(cfr[nt][3] + b2b) * w3b;
            }
            p_lo += __shfl_down_sync(0xffffffffu, p_lo, 2, 4);
            p_lo += __shfl_down_sync(0xffffffffu, p_lo, 1, 4);
            p_hi += __shfl_down_sync(0xffffffffu, p_hi, 2, 4);
            p_hi += __shfl_down_sync(0xffffffffu, p_hi, 1, 4);
            if (tig == 0) {
                sm.bm.red[ra + gid][wn] = p_lo;
                sm.bm.red[ra + gid + 8][wn] = p_hi;
            }
            __syncthreads();
            if (tid < 32) {
                int l = l0 + tid;
                if (l < LL) {
                    float s = sm.bm.red[tid][0] + sm.bm.red[tid][1]
                            + sm.bm.red[tid][2] + sm.bm.red[tid][3] + b3[0];
                    g_scores[b * LL + l] = s;
                }
            }
        }
        grid_sync();

        // ======== P3: softmax + z (128 units = 32 b x 4 d-chunks(128)) ========
        if (bid < 128) {
            int b = bid >> 2;
            int dch = bid & 3;
            float v = (tid < LL) ? g_scores[b * LL + tid] : -1e30f;
            float m = v;
#pragma unroll
            for (int off = 16; off; off >>= 1) m = fmaxf(m, __shfl_xor_sync(0xffffffffu, m, off));
            if (lane == 0) sm.c.red[w] = m;
            __syncthreads();
            m = sm.c.red[0];
#pragma unroll
            for (int i = 1; i < 8; i++) m = fmaxf(m, sm.c.red[i]);
            float e = (tid < LL) ? expf(v - m) : 0.f;
            __syncthreads();
            float sum = e;
#pragma unroll
            for (int off = 16; off; off >>= 1) sum += __shfl_xor_sync(0xffffffffu, sum, off);
            if (lane == 0) sm.c.red[w] = sum;
            __syncthreads();
            sum = sm.c.red[0] + sm.c.red[1] + sm.c.red[2] + sm.c.red[3]
                + sm.c.red[4] + sm.c.red[5] + sm.c.red[6] + sm.c.red[7];
            float inv = 1.f / sum;
            if (tid < LL) sm.c.al[tid] = e * inv;
            __syncthreads();
            int dl = tid & 127;
            int lh = tid >> 7;
            int d = dch * 128 + dl;
            const float* ab = a_feat + (size_t)(b * LL + lh * 98) * DD + d;
            const float* alv = &sm.c.al[lh * 98];
            float acc = 0.f;
#pragma unroll 14
            for (int l = 0; l < 98; l++) acc += alv[l] * __ldcg(&ab[(size_t)l * DD]);
            sm.c.cpart[lh][dl] = acc;
            __syncthreads();
            if (tid < 128) {
                float zv = sm.c.cpart[0][tid] + sm.c.cpart[1][tid];
                int dg = dch * 128 + tid;
                g_z[b * DD + dg] = zv;
                g_hze[(size_t)(b * TT + t) * HZE + HH + dg] = zv;
            }
        }
        grid_sync();

        // ======== P4: LSTM via mma (16 blocks = 2 m-halves x 8 jp-blocks) =====
        // warp = m16 x 4 gate-tiles at n = gate*512 + jp8 -> i,f,g,o in-register,
        // inline pointwise update. A (z tile) staged in smem, conflict-free.
        if (bid < 16) {
            int mh = bid & 1;
            int jblk = bid >> 1;              // 0..7
            for (int i = tid; i < 16 * DD; i += NTHR) {
                int r = i >> 9, k = i & 511;
                sm.tt.a16[r][k] = f2tf32(g_z[(mh * 16 + r) * DD + k]);
            }
            __syncthreads();
            int jpb = (jblk * 8 + w) * 8;     // jp base 0..504
            float cfr[4][4] = {};             // [gate][reg]
#pragma unroll 4
            for (int ks = 0; ks < 64; ks++) {
                int k0 = ks * 8;
                uint32_t a0 = sm.tt.a16[gid][k0 + tig];
                uint32_t a1 = sm.tt.a16[gid + 8][k0 + tig];
                uint32_t a2r = sm.tt.a16[gid][k0 + tig + 4];
                uint32_t a3 = sm.tt.a16[gid + 8][k0 + tig + 4];
                const uint32_t* wb0 = &g_wiht[(k0 + tig) * GG + jpb + gid];
                const uint32_t* wb1 = &g_wiht[(k0 + tig + 4) * GG + jpb + gid];
#pragma unroll
                for (int gate = 0; gate < 4; gate++) {
                    uint32_t b0 = wb0[gate * 512];
                    uint32_t b1 = wb1[gate * 512];
                    mma_tf32(cfr[gate], a0, a1, a2r, a3, b0, b1);
                }
            }
#pragma unroll
            for (int half = 0; half < 2; half++) {
                int b = mh * 16 + gid + half * 8;
                int creg = half * 2;
                const float* eg = g_egate + (size_t)(b * TT + t) * GG;
                const float* hg = g_hpg + b * NPG + A1;
#pragma unroll
                for (int jj = 0; jj < 2; jj++) {
                    int jp = jpb + tig * 2 + jj;
                    float ai = cfr[0][creg + jj] + eg[jp]        + hg[jp];
                    float af = cfr[1][creg + jj] + eg[jp + 512]  + hg[jp + 512];
                    float ag = cfr[2][creg + jj] + eg[jp + 1024] + hg[jp + 1024];
                    float ao = cfr[3][creg + jj] + eg[jp + 1536] + hg[jp + 1536];
                    float i_ = 1.f / (1.f + expf(-ai));
                    float f_ = 1.f / (1.f + expf(-af));
                    float o_ = 1.f / (1.f + expf(-ao));
                    float gv = tanhf(ag);
                    float c = f_ * g_c[b * HH + jp] + i_ * gv;
                    float h = o_ * tanhf(c);
                    g_c[b * HH + jp] = c;
                    g_h[b * HH + jp] = h;
                    g_hze[(size_t)(b * TT + t) * HZE + jp] = h;
                }
            }
            __syncthreads();
        }
        grid_sync();
    }
}

// ---------------- launch ----------------
extern "C" void kernel_launch(void* const* d_in, const int* in_sizes, int n_in,
                              void* d_out, int out_size) {
    const float* a      = (const float*)d_in[0];
    const float* h0     = (const float*)d_in[1];
    const float* c0     = (const float*)d_in[2];
    const int*   y      = (const int*)d_in[3];
    const float* att_w1 = (const float*)d_in[4];
    const float* att_b1 = (const float*)d_in[5];
    const float* att_w2 = (const float*)d_in[6];
    const float* att_b2 = (const float*)d_in[7];
    const float* att_w3 = (const float*)d_in[8];
    const float* att_b3 = (const float*)d_in[9];
    const float* w_ih   = (const float*)d_in[10];
    const float* w_hh   = (const float*)d_in[11];
    const float* b_ih   = (const float*)d_in[12];
    const float* b_hh   = (const float*)d_in[13];
    const float* embed  = (const float*)d_in[14];
    const float* out_w1 = (const float*)d_in[15];
    const float* out_b1 = (const float*)d_in[16];
    const float* out_w2 = (const float*)d_in[17];
    const float* out_b2 = (const float*)d_in[18];
    const float* out_w3 = (const float*)d_in[19];
    const float* out_b3 = (const float*)d_in[20];
    float* out = (float*)d_out;

    float *prea, *eseq, *egate, *hze, *x1, *x2;
    uint32_t *w2t, *w1ht, *whht, *wiht;
    cudaGetSymbolAddress((void**)&prea,  g_prea);
    cudaGetSymbolAddress((void**)&eseq,  g_eseq);
    cudaGetSymbolAddress((void**)&egate, g_egate);
    cudaGetSymbolAddress((void**)&hze,   g_hze);
    cudaGetSymbolAddress((void**)&x1,    g_x1);
    cudaGetSymbolAddress((void**)&x2,    g_x2);
    cudaGetSymbolAddress((void**)&w2t,   g_w2t);
    cudaGetSymbolAddress((void**)&w1ht,  g_w1ht);
    cudaGetSymbolAddress((void**)&whht,  g_whht);
    cudaGetSymbolAddress((void**)&wiht,  g_wiht);

    k_embed<<<BB * TT, EE>>>(y, embed);
    k_cvt<<<(A1 * A2) / 256, 256>>>(w2t, att_w2);
    k_cvt<<<(HH * A1) / 256, 256>>>(w1ht, att_w1 + (size_t)DD * A1);
    k_cvt<<<(HH * GG) / 256, 256>>>(whht, w_hh);
    k_cvt<<<(DD * GG) / 256, 256>>>(wiht, w_ih);

    k_sgemm<0><<<dim3((A1 + 63) / 64, (BB * LL + 63) / 64), 256>>>(
        a, DD, att_w1, A1, att_b1, prea, A1, BB * LL, A1, DD);
    k_sgemm<0><<<dim3((GG + 63) / 64, (BB * TT + 63) / 64), 256>>>(
        eseq, EE, w_ih + (size_t)DD * GG, GG, b_ih, egate, GG, BB * TT, GG, EE);

    k_steps<<<NBLK, NTHR>>>(a, h0, c0, b_hh, att_b2, att_w3, att_b3);

    k_sgemm<1><<<dim3((NH + 63) / 64, (BB * TT + 63) / 64), 256>>>(
        hze, HZE, out_w1, NH, out_b1, x1, NH, BB * TT, NH, HZE);
    k_sgemm<1><<<dim3((NH + 63) / 64, (BB * TT + 63) / 64), 256>>>(
        x1, NH, out_w2, NH, out_b2, x2, NH, BB * TT, NH, NH);
    k_sgemm<0><<<dim3((VV + 63) / 64, (BB * TT + 63) / 64), 256>>>(
        x2, NH, out_w3, VV, out_b3, out, VV, BB * TT, VV, NH);
}

// round 17
// speedup vs baseline: 1.9629x; 1.1667x over previous
#include <cuda_runtime.h>
#include <math.h>
#include <stdint.h>

#define BB 32
#define LL 196
#define DD 512
#define HH 512
#define EE 256
#define TT 128
#define VV 512
#define A1 256
#define A2 128
#define GG 2048            // 4*H
#define NH 358
#define NHP 384            // padded NH (mult of 64)
#define HZE (HH + DD + EE) // 1280
#define NPG (A1 + GG)      // 2304
#define PADTOK 0
#define NBLK 296
#define NTHR 256
#define NGRP 37            // 296 / 8
#define XPA 260            // x1t row stride (tf32): 260 mod 32 = 4 -> conflict-free a-frag LDS

// ---------------- scratch (no allocation allowed) ----------------
__device__ float g_eseq[BB * TT * EE];
__device__ float g_prea[BB * LL * A1];
__device__ float g_egate[BB * TT * GG];
__device__ float g_h[BB * HH];
__device__ float g_c[BB * HH];
__device__ float g_hpg[BB * NPG];
__device__ float g_scores[BB * LL];
__device__ float g_z[BB * DD];
__device__ float g_hze[BB * TT * HZE];
__device__ float g_x1[BB * TT * NHP];
__device__ float g_x2[BB * TT * NHP];
__device__ uint32_t g_w2t[A1 * A2];       // att_w2 tf32 [k*128+n]  (step-loop P2)
__device__ uint32_t g_wa1[DD * A1];       // att_w1[:D] tf32 [k*256+n]
__device__ uint32_t g_wihE[EE * GG];      // w_ih[D:] tf32 [k*2048+n]
__device__ uint32_t g_w1p[HZE * NHP];     // out_w1 tf32 padded [k*384+n]
__device__ uint32_t g_w2p[NHP * NHP];     // out_w2 tf32 padded [k*384+n]
__device__ uint32_t g_w3p[NHP * VV];      // out_w3 tf32 padded [k*512+n]

// ---------------- hierarchical grid barrier (generation-tagged) ----------------
__device__ unsigned g_cnt0[NGRP];
__device__ unsigned g_cnt1;
__device__ volatile unsigned g_bar_gen;

__device__ __forceinline__ void grid_sync() {
    __syncthreads();
    if (threadIdx.x == 0) {
        unsigned gen = g_bar_gen;
        __threadfence();
        unsigned grp = (unsigned)blockIdx.x >> 3;
        unsigned old = atomicAdd(&g_cnt0[grp], 1u);
        bool done = false;
        if (old == 8u * gen + 7u) {
            unsigned o1 = atomicAdd(&g_cnt1, 1u);
            if (o1 == (unsigned)NGRP * gen + (NGRP - 1u)) {
                __threadfence();
                g_bar_gen = gen + 1u;
                done = true;
            }
        }
        if (!done) while (g_bar_gen == gen) {}
        __threadfence();
    }
    __syncthreads();
}

__device__ __forceinline__ float tanh_fast(float x) {
    float y;
    asm("tanh.approx.f32 %0, %1;" : "=f"(y) : "f"(x));
    return y;
}

__device__ __forceinline__ uint32_t f2tf32(float x) {
    uint32_t r;
    asm("cvt.rna.tf32.f32 %0, %1;" : "=r"(r) : "f"(x));
    return r;
}

__device__ __forceinline__ void mma_tf32(float c[4], uint32_t a0, uint32_t a1,
                                         uint32_t a2, uint32_t a3,
                                         uint32_t b0, uint32_t b1) {
    asm volatile(
        "mma.sync.aligned.m16n8k8.row.col.f32.tf32.tf32.f32 "
        "{%0,%1,%2,%3}, {%4,%5,%6,%7}, {%8,%9}, {%0,%1,%2,%3};"
        : "+f"(c[0]), "+f"(c[1]), "+f"(c[2]), "+f"(c[3])
        : "r"(a0), "r"(a1), "r"(a2), "r"(a3), "r"(b0), "r"(b1));
}

// ---------------- weight -> tf32 conversion (once per launch) ----------------
__global__ void k_cvt(uint32_t* __restrict__ dst, const float* __restrict__ src) {
    int i = blockIdx.x * 256 + threadIdx.x;
    dst[i] = f2tf32(src[i]);
}

// padded convert: dst[Kp x Np], src[Ksrc x Nsrc] (row stride srcld), zeros outside
__global__ void k_cvt_pad(uint32_t* __restrict__ dst, const float* __restrict__ src,
                          int Ksrc, int Nsrc, int srcld, int Np) {
    int i = blockIdx.x * 256 + threadIdx.x;
    int k = i / Np, n = i % Np;
    float v = (k < Ksrc && n < Nsrc) ? src[(size_t)k * srcld + n] : 0.f;
    dst[i] = f2tf32(v);
}

// ---------------- embedding gather (shift-right w/ pad) ----------------
__global__ void k_embed(const int* __restrict__ y, const float* __restrict__ embed) {
    int bt = blockIdx.x;
    int b = bt / TT, t = bt % TT;
    int tok = (t == 0) ? PADTOK : y[b * TT + (t - 1)];
    float v = embed[tok * EE + threadIdx.x];
    g_eseq[bt * EE + threadIdx.x] = v;
    g_hze[bt * HZE + HH + DD + threadIdx.x] = v;
}

// ---------------- tf32 mma GEMM: C = act(A*Bt + bias) ----------------
// A fp32 [M x K] (lda), Bt tf32 [K x ldb], C fp32 [M x ldc].
// grid = (N/64, M/32); K multiple of 64. Cols >= Nreal written as 0 (ACT any).
template <int ACT>
__global__ void __launch_bounds__(256) k_tgemm(
    const float* __restrict__ A, int lda,
    const uint32_t* __restrict__ Bt, int ldb,
    const float* __restrict__ bias, int Nreal,
    float* __restrict__ C, int ldc, int K)
{
    __shared__ uint32_t As[32][68];      // 68 mod 32 = 4 -> conflict-free a-frag LDS
    int tid = threadIdx.x;
    int lane = tid & 31, w = tid >> 5;
    int gid = lane >> 2, tig = lane & 3;
    int row0 = blockIdx.y * 32;
    int col0 = blockIdx.x * 64;
    int wm = w & 1, wn = w >> 1;         // wm: m16 half, wn: 0..3 (n16 each)
    int ra = wm * 16;
    float cfr[2][4] = {};
    for (int kc = 0; kc < K; kc += 64) {
        for (int q = tid; q < 512; q += 256) {
            int r = q >> 4, kq = (q & 15) * 4;
            float4 v = *reinterpret_cast<const float4*>(&A[(size_t)(row0 + r) * lda + kc + kq]);
            As[r][kq] = f2tf32(v.x);
            As[r][kq + 1] = f2tf32(v.y);
            As[r][kq + 2] = f2tf32(v.z);
            As[r][kq + 3] = f2tf32(v.w);
        }
        __syncthreads();
#pragma unroll
        for (int ks = 0; ks < 8; ks++) {
            int k0 = ks * 8;
            uint32_t a0 = As[ra + gid][k0 + tig];
            uint32_t a1 = As[ra + gid + 8][k0 + tig];
            uint32_t a2r = As[ra + gid][k0 + tig + 4];
            uint32_t a3 = As[ra + gid + 8][k0 + tig + 4];
            const uint32_t* wb0 = &Bt[(size_t)(kc + k0 + tig) * ldb + col0 + wn * 16 + gid];
            const uint32_t* wb1 = &Bt[(size_t)(kc + k0 + tig + 4) * ldb + col0 + wn * 16 + gid];
            mma_tf32(cfr[0], a0, a1, a2r, a3, wb0[0], wb1[0]);
            mma_tf32(cfr[1], a0, a1, a2r, a3, wb0[8], wb1[8]);
        }
        __syncthreads();
    }
#pragma unroll
    for (int nt = 0; nt < 2; nt++) {
        int cA = col0 + wn * 16 + nt * 8 + tig * 2;
#pragma unroll
        for (int half = 0; half < 2; half++) {
            int r = row0 + ra + gid + half * 8;
#pragma unroll
            for (int jj = 0; jj < 2; jj++) {
                int c = cA + jj;
                if (c < ldc) {
                    float v = 0.f;
                    if (c < Nreal) {
                        v = cfr[nt][half * 2 + jj] + bias[c];
                        if (ACT == 1) v = tanhf(v);
                    }
                    C[(size_t)r * ldc + c] = v;
                }
            }
        }
    }
}

// ---------------- persistent step-loop kernel (EXACT R12) ----------------
struct SmemA1 { float h1[HH]; };
struct SmemA2 { float h4[4][HH]; };
struct SmemBm { uint32_t x1t[32][XPA]; float red[32][4]; };
struct SmemC  { float al[LL]; float red[8]; float cpart[2][128]; };
struct SmemD  { float zs[4][DD]; float gacc[4][4][16]; };
union StepSmem { SmemA1 a1; SmemA2 a2; SmemBm bm; SmemC c; SmemD d; };

__global__ __launch_bounds__(NTHR, 2)
void k_steps(const float* __restrict__ a_feat,
             const float* __restrict__ h0, const float* __restrict__ c0,
             const float* __restrict__ w1h,   // att_w1 + D*A1 (ld A1)
             const float* __restrict__ whh,   // ld GG
             const float* __restrict__ bhh,
             const float* __restrict__ b2,
             const float* __restrict__ w3, const float* __restrict__ b3,
             const float* __restrict__ wih) {
    __shared__ StepSmem sm;
    int bid = blockIdx.x;
    int tid = threadIdx.x;
    int lane = tid & 31, w = tid >> 5;
    int gid = lane >> 2, tig = lane & 3;

    for (int i = bid * NTHR + tid; i < BB * HH; i += NBLK * NTHR) {
        g_h[i] = h0[i];
        g_c[i] = c0[i];
    }
    grid_sync();

    for (int t = 0; t < TT; t++) {
        // ======== P1: A1 (32 units) + A2 (256 units: 64 cols x 4 b) ========
        if (bid < 32) {
            int b = bid;
            for (int i = tid; i < HH; i += NTHR) sm.a1.h1[i] = g_h[b * HH + i];
            __syncthreads();
            float acc = 0.f;
#pragma unroll 16
            for (int k = 0; k < HH; k++)
                acc += sm.a1.h1[k] * __ldcg(&w1h[k * A1 + tid]);
            g_hpg[b * NPG + tid] = acc;
        } else if (bid < 288) {
            int a2u = bid - 32;
            int cch = a2u >> 3;
            int bg = a2u & 7;
            for (int i = tid; i < 4 * HH; i += NTHR) {
                int bi = i >> 9, kk = i & 511;
                sm.a2.h4[bi][kk] = g_h[(bg * 4 + bi) * HH + kk];
            }
            __syncthreads();
            int col = cch * 64 + (tid & 63);
            int bi = tid >> 6;
            const float* hrow = sm.a2.h4[bi];
            float acc = bhh[col];
#pragma unroll 32
            for (int k = 0; k < HH; k++)
                acc += hrow[k] * __ldcg(&whh[(size_t)k * GG + col]);
            g_hpg[(bg * 4 + bi) * NPG + A1 + col] = acc;
        }
        grid_sync();

        // ======== P2: attention via tf32 mma (224 units = 32 b x 7 l-tiles(32))
        if (bid < 224) {
            int b = bid / 7;
            int l0 = (bid % 7) * 32;
            {
                float hpk = g_hpg[b * NPG + tid];
                const float* pr = g_prea + (size_t)(b * LL + l0) * A1 + tid;
#pragma unroll 8
                for (int r = 0; r < 32; r++) {
                    int l = l0 + r;
                    float v = 0.f;
                    if (l < LL) v = tanh_fast(__ldcg(&pr[(size_t)r * A1]) + hpk);
                    sm.bm.x1t[r][tid] = f2tf32(v);
                }
            }
            __syncthreads();
            int wm = w & 1;
            int wn = w >> 1;
            int ra = wm * 16;
            float cfr[4][4] = {};
#pragma unroll 4
            for (int ks = 0; ks < 32; ks++) {
                int k0 = ks * 8;
                uint32_t a0 = sm.bm.x1t[ra + gid][k0 + tig];
                uint32_t a1 = sm.bm.x1t[ra + gid + 8][k0 + tig];
                uint32_t a2r = sm.bm.x1t[ra + gid][k0 + tig + 4];
                uint32_t a3 = sm.bm.x1t[ra + gid + 8][k0 + tig + 4];
                const uint32_t* wb0 = &g_w2t[(k0 + tig) * A2 + wn * 32 + gid];
                const uint32_t* wb1 = &g_w2t[(k0 + tig + 4) * A2 + wn * 32 + gid];
#pragma unroll
                for (int nt = 0; nt < 4; nt++) {
                    uint32_t b0 = wb0[nt * 8];
                    uint32_t b1 = wb1[nt * 8];
                    mma_tf32(cfr[nt], a0, a1, a2r, a3, b0, b1);
                }
            }
            float p_lo = 0.f, p_hi = 0.f;
#pragma unroll
            for (int nt = 0; nt < 4; nt++) {
                int cA = wn * 32 + nt * 8 + tig * 2;
                float b2a = b2[cA], b2b = b2[cA + 1];
                float w3a = w3[cA], w3b = w3[cA + 1];
                p_lo += tanh_fast(cfr[nt][0] + b2a) * w3a + tanh_fast(cfr[nt][1] + b2b) * w3b;
                p_hi += tanh_fast(cfr[nt][2] + b2a) * w3a + tanh_fast(cfr[nt][3] + b2b) * w3b;
            }
            p_lo += __shfl_down_sync(0xffffffffu, p_lo, 2, 4);
            p_lo += __shfl_down_sync(0xffffffffu, p_lo, 1, 4);
            p_hi += __shfl_down_sync(0xffffffffu, p_hi, 2, 4);
            p_hi += __shfl_down_sync(0xffffffffu, p_hi, 1, 4);
            if (tig == 0) {
                sm.bm.red[ra + gid][wn] = p_lo;
                sm.bm.red[ra + gid + 8][wn] = p_hi;
            }
            __syncthreads();
            if (tid < 32) {
                int l = l0 + tid;
                if (l < LL) {
                    float s = sm.bm.red[tid][0] + sm.bm.red[tid][1]
                            + sm.bm.red[tid][2] + sm.bm.red[tid][3] + b3[0];
                    g_scores[b * LL + l] = s;
                }
            }
        }
        grid_sync();

        // ======== P3: softmax + z (128 units = 32 b x 4 d-chunks(128)) ========
        if (bid < 128) {
            int b = bid >> 2;
            int dch = bid & 3;
            float v = (tid < LL) ? g_scores[b * LL + tid] : -1e30f;
            float m = v;
#pragma unroll
            for (int off = 16; off; off >>= 1) m = fmaxf(m, __shfl_xor_sync(0xffffffffu, m, off));
            if (lane == 0) sm.c.red[w] = m;
            __syncthreads();
            m = sm.c.red[0];
#pragma unroll
            for (int i = 1; i < 8; i++) m = fmaxf(m, sm.c.red[i]);
            float e = (tid < LL) ? expf(v - m) : 0.f;
            __syncthreads();
            float sum = e;
#pragma unroll
            for (int off = 16; off; off >>= 1) sum += __shfl_xor_sync(0xffffffffu, sum, off);
            if (lane == 0) sm.c.red[w] = sum;
            __syncthreads();
            sum = sm.c.red[0] + sm.c.red[1] + sm.c.red[2] + sm.c.red[3]
                + sm.c.red[4] + sm.c.red[5] + sm.c.red[6] + sm.c.red[7];
            float inv = 1.f / sum;
            if (tid < LL) sm.c.al[tid] = e * inv;
            __syncthreads();
            int dl = tid & 127;
            int lh = tid >> 7;
            int d = dch * 128 + dl;
            const float* ab = a_feat + (size_t)(b * LL + lh * 98) * DD + d;
            const float* alv = &sm.c.al[lh * 98];
            float acc = 0.f;
#pragma unroll 14
            for (int l = 0; l < 98; l++) acc += alv[l] * __ldcg(&ab[(size_t)l * DD]);
            sm.c.cpart[lh][dl] = acc;
            __syncthreads();
            if (tid < 128) {
                float zv = sm.c.cpart[0][tid] + sm.c.cpart[1][tid];
                int dg = dch * 128 + tid;
                g_z[b * DD + dg] = zv;
                g_hze[(size_t)(b * TT + t) * HZE + HH + dg] = zv;
            }
        }
        grid_sync();

        // ======== P4: LSTM (256 units = 32 jp-chunks(16) x 8 bg(4)) ===========
        if (bid < 256) {
            int jpch = bid >> 3;
            int bg = bid & 7;
            for (int i = tid; i < 4 * DD; i += NTHR) {
                int bi = i >> 9, kk = i & 511;
                sm.d.zs[bi][kk] = g_z[(bg * 4 + bi) * DD + kk];
            }
            __syncthreads();
            int jl = tid & 15;
            int gate = (tid >> 4) & 3;
            int bi = tid >> 6;
            int jp = jpch * 16 + jl;
            const float* Wg = wih + (size_t)gate * HH + jp;
            const float* zrow = sm.d.zs[bi];
            float acc = 0.f;
#pragma unroll 32
            for (int d = 0; d < DD; d++)
                acc += zrow[d] * __ldcg(&Wg[(size_t)d * GG]);
            sm.d.gacc[gate][bi][jl] = acc;
            __syncthreads();
            if (tid < 64) {
                int jl2 = tid & 15;
                int bi2 = tid >> 4;
                int b = bg * 4 + bi2;
                int jp2 = jpch * 16 + jl2;
                const float* eg = g_egate + (size_t)(b * TT + t) * GG;
                const float* hg = g_hpg + b * NPG + A1;
                float ai = sm.d.gacc[0][bi2][jl2] + eg[jp2]        + hg[jp2];
                float af = sm.d.gacc[1][bi2][jl2] + eg[jp2 + 512]  + hg[jp2 + 512];
                float ag = sm.d.gacc[2][bi2][jl2] + eg[jp2 + 1024] + hg[jp2 + 1024];
                float ao = sm.d.gacc[3][bi2][jl2] + eg[jp2 + 1536] + hg[jp2 + 1536];
                float i_ = 1.f / (1.f + expf(-ai));
                float f_ = 1.f / (1.f + expf(-af));
                float o_ = 1.f / (1.f + expf(-ao));
                float gv = tanhf(ag);
                float c = f_ * g_c[b * HH + jp2] + i_ * gv;
                float h = o_ * tanhf(c);
                g_c[b * HH + jp2] = c;
                g_h[b * HH + jp2] = h;
                g_hze[(size_t)(b * TT + t) * HZE + jp2] = h;
            }
        }
        grid_sync();
    }
}

// ---------------- launch ----------------
extern "C" void kernel_launch(void* const* d_in, const int* in_sizes, int n_in,
                              void* d_out, int out_size) {
    const float* a      = (const float*)d_in[0];
    const float* h0     = (const float*)d_in[1];
    const float* c0     = (const float*)d_in[2];
    const int*   y      = (const int*)d_in[3];
    const float* att_w1 = (const float*)d_in[4];
    const float* att_b1 = (const float*)d_in[5];
    const float* att_w2 = (const float*)d_in[6];
    const float* att_b2 = (const float*)d_in[7];
    const float* att_w3 = (const float*)d_in[8];
    const float* att_b3 = (const float*)d_in[9];
    const float* w_ih   = (const float*)d_in[10];
    const float* w_hh   = (const float*)d_in[11];
    const float* b_ih   = (const float*)d_in[12];
    const float* b_hh   = (const float*)d_in[13];
    const float* embed  = (const float*)d_in[14];
    const float* out_w1 = (const float*)d_in[15];
    const float* out_b1 = (const float*)d_in[16];
    const float* out_w2 = (const float*)d_in[17];
    const float* out_b2 = (const float*)d_in[18];
    const float* out_w3 = (const float*)d_in[19];
    const float* out_b3 = (const float*)d_in[20];
    float* out = (float*)d_out;

    float *prea, *eseq, *egate, *hze, *x1, *x2;
    uint32_t *w2t, *wa1, *wihE, *w1p, *w2p, *w3p;
    cudaGetSymbolAddress((void**)&prea,  g_prea);
    cudaGetSymbolAddress((void**)&eseq,  g_eseq);
    cudaGetSymbolAddress((void**)&egate, g_egate);
    cudaGetSymbolAddress((void**)&hze,   g_hze);
    cudaGetSymbolAddress((void**)&x1,    g_x1);
    cudaGetSymbolAddress((void**)&x2,    g_x2);
    cudaGetSymbolAddress((void**)&w2t,   g_w2t);
    cudaGetSymbolAddress((void**)&wa1,   g_wa1);
    cudaGetSymbolAddress((void**)&wihE,  g_wihE);
    cudaGetSymbolAddress((void**)&w1p,   g_w1p);
    cudaGetSymbolAddress((void**)&w2p,   g_w2p);
    cudaGetSymbolAddress((void**)&w3p,   g_w3p);

    k_embed<<<BB * TT, EE>>>(y, embed);

    // weight conversions
    k_cvt<<<(A1 * A2) / 256, 256>>>(w2t, att_w2);
    k_cvt<<<(DD * A1) / 256, 256>>>(wa1, att_w1);                    // rows 0..511
    k_cvt<<<(EE * GG) / 256, 256>>>(wihE, w_ih + (size_t)DD * GG);
    k_cvt_pad<<<(HZE * NHP) / 256, 256>>>(w1p, out_w1, HZE, NH, NH, NHP);
    k_cvt_pad<<<(NHP * NHP) / 256, 256>>>(w2p, out_w2, NH, NH, NH, NHP);
    k_cvt_pad<<<(NHP * VV) / 256, 256>>>(w3p, out_w3, NH, VV, VV, VV);

    // pre GEMMs (tf32 mma)
    k_tgemm<0><<<dim3(A1 / 64, BB * LL / 32), 256>>>(
        a, DD, wa1, A1, att_b1, A1, prea, A1, DD);
    k_tgemm<0><<<dim3(GG / 64, BB * TT / 32), 256>>>(
        eseq, EE, wihE, GG, b_ih, GG, egate, GG, EE);

    // persistent step loop (all 128 timesteps)
    k_steps<<<NBLK, NTHR>>>(a, h0, c0,
                            att_w1 + (size_t)DD * A1, w_hh, b_hh,
                            att_b2, att_w3, att_b3, w_ih);

    // output MLP (tf32 mma): hze(1280) -> 358 tanh -> 358 tanh -> 512
    k_tgemm<1><<<dim3(NHP / 64, BB * TT / 32), 256>>>(
        hze, HZE, w1p, NHP, out_b1, NH, x1, NHP, HZE);
    k_tgemm<1><<<dim3(NHP / 64, BB * TT / 32), 256>>>(
        x1, NHP, w2p, NHP, out_b2, NH, x2, NHP, NHP);
    k_tgemm<0><<<dim3(VV / 64, BB * TT / 32), 256>>>(
        x2, NHP, w3p, VV, out_b3, VV, out, VV, NHP);
}